// round 5
// baseline (speedup 1.0000x reference)
#include <cuda_runtime.h>

// LSTM_16638703305445: B=4096, T=365, IN=32, H=256, OUT=1
// Persistent per-CTA batch-sliced LSTM scan. 256 CTAs x 256 threads.
// Thread j owns hidden unit j for the CTA's 16 batch rows; gates accumulate
// as packed f32x2 pairs (FFMA2) to hit the full 128 FMA/cyc/SM fp32 rate.

#define T_STEPS 365
#define IN_DIM  32
#define H_DIM   256
#define B_BLK   16   // batch rows per CTA
#define NB      8    // f32x2 pairs per thread (16 batch rows)

typedef unsigned long long u64;

__device__ __forceinline__ u64 fma2(u64 a, u64 b, u64 c) {
    u64 d;
    asm("fma.rn.f32x2 %0, %1, %2, %3;" : "=l"(d) : "l"(a), "l"(b), "l"(c));
    return d;
}
__device__ __forceinline__ u64 bc2(float x) {
    u64 d;
    asm("mov.b64 %0, {%1, %1};" : "=l"(d) : "f"(x));
    return d;
}
__device__ __forceinline__ void unpack2(u64 v, float& lo, float& hi) {
    asm("mov.b64 {%0, %1}, %2;" : "=f"(lo), "=f"(hi) : "l"(v));
}
__device__ __forceinline__ float sigm(float x) {
    return __fdividef(1.0f, 1.0f + __expf(-x));
}
__device__ __forceinline__ float tanh_acc(float x) {
    float a = fabsf(x);
    float e = __expf(-2.0f * a);
    float r = __fdividef(1.0f - e, 1.0f + e);
    return copysignf(r, x);
}
__device__ __forceinline__ float f4c(const float4 v, int kk) {
    return kk == 0 ? v.x : kk == 1 ? v.y : kk == 2 ? v.z : v.w;
}

__global__ void __launch_bounds__(256, 2)
lstm_scan_kernel(const float* __restrict__ xd,    // [B, T, IN]
                 const float* __restrict__ w_ih,  // [4H, IN]
                 const float* __restrict__ w_hh,  // [4H, H]
                 const float* __restrict__ bias,  // [4H]
                 const float* __restrict__ w_out, // [1, H]
                 const float* __restrict__ b_out, // [1]
                 float* __restrict__ out)         // [B, 1]
{
    __shared__ float h_s[H_DIM * B_BLK];   // [k][b] layout, 16 KB
    __shared__ float x_s[IN_DIM * B_BLK];  // [i][b] layout, 2 KB

    const int j  = threadIdx.x;          // hidden unit 0..255
    const int B0 = blockIdx.x * B_BLK;   // batch base for this CTA

    // init state
    #pragma unroll
    for (int b = 0; b < B_BLK; b++) h_s[j * B_BLK + b] = 0.0f;
    float c[B_BLK];
    #pragma unroll
    for (int b = 0; b < B_BLK; b++) c[b] = 0.0f;

    const u64 bi2 = bc2(bias[j]);
    const u64 bf2 = bc2(bias[H_DIM + j]);
    const u64 bg2 = bc2(bias[2 * H_DIM + j]);
    const u64 bo2 = bc2(bias[3 * H_DIM + j]);

    // W_hh row bases in float4 units (row stride = 64 float4; gate offset = 16384)
    const float4* Wb = (const float4*)w_hh + (size_t)j * (H_DIM / 4);
    // w_ih row bases in float4 units (row stride = 8 float4; gate offset = 2048)
    const float4* Ub = (const float4*)w_ih + (size_t)j * (IN_DIM / 4);

    __syncthreads();

    for (int t = 0; t < T_STEPS; t++) {
        // ---- load x tile for this step: 16 rows x 32 floats, transposed to [i][b]
        {
            int e = j;                    // elements j and j+256 of 512
            int b = e >> 5, i = e & 31;
            float v0 = __ldg(&xd[(size_t)(B0 + b) * (T_STEPS * IN_DIM) + t * IN_DIM + i]);
            int e2 = j + 256;
            int b2 = e2 >> 5, i2 = e2 & 31;
            float v1 = __ldg(&xd[(size_t)(B0 + b2) * (T_STEPS * IN_DIM) + t * IN_DIM + i2]);
            x_s[i * B_BLK + b]   = v0;
            x_s[i2 * B_BLK + b2] = v1;
        }
        __syncthreads();  // x ready; also orders previous step's h writes

        u64 ai[NB], af[NB], ag[NB], ao[NB];
        #pragma unroll
        for (int p = 0; p < NB; p++) { ai[p] = bi2; af[p] = bf2; ag[p] = bg2; ao[p] = bo2; }

        // ---- input projection: 8 chunks of 4 over IN=32
        #pragma unroll 2
        for (int kc = 0; kc < IN_DIM / 4; kc++) {
            float4 wi4 = __ldg(Ub + kc);
            float4 wf4 = __ldg(Ub + kc + 2048);
            float4 wg4 = __ldg(Ub + kc + 4096);
            float4 wo4 = __ldg(Ub + kc + 6144);
            #pragma unroll
            for (int kk = 0; kk < 4; kk++) {
                const ulonglong2* hp = (const ulonglong2*)(x_s + (kc * 4 + kk) * B_BLK);
                ulonglong2 h0 = hp[0], h1 = hp[1], h2 = hp[2], h3 = hp[3];
                u64 wib = bc2(f4c(wi4, kk));
                u64 wfb = bc2(f4c(wf4, kk));
                u64 wgb = bc2(f4c(wg4, kk));
                u64 wob = bc2(f4c(wo4, kk));
                u64 hv[NB] = {h0.x, h0.y, h1.x, h1.y, h2.x, h2.y, h3.x, h3.y};
                #pragma unroll
                for (int p = 0; p < NB; p++) {
                    ai[p] = fma2(hv[p], wib, ai[p]);
                    af[p] = fma2(hv[p], wfb, af[p]);
                    ag[p] = fma2(hv[p], wgb, ag[p]);
                    ao[p] = fma2(hv[p], wob, ao[p]);
                }
            }
        }

        // ---- recurrent projection: 64 chunks of 4 over H=256
        #pragma unroll 2
        for (int kc = 0; kc < H_DIM / 4; kc++) {
            float4 wi4 = __ldg(Wb + kc);
            float4 wf4 = __ldg(Wb + kc + 16384);
            float4 wg4 = __ldg(Wb + kc + 32768);
            float4 wo4 = __ldg(Wb + kc + 49152);
            #pragma unroll
            for (int kk = 0; kk < 4; kk++) {
                const ulonglong2* hp = (const ulonglong2*)(h_s + (kc * 4 + kk) * B_BLK);
                ulonglong2 h0 = hp[0], h1 = hp[1], h2 = hp[2], h3 = hp[3];
                u64 wib = bc2(f4c(wi4, kk));
                u64 wfb = bc2(f4c(wf4, kk));
                u64 wgb = bc2(f4c(wg4, kk));
                u64 wob = bc2(f4c(wo4, kk));
                u64 hv[NB] = {h0.x, h0.y, h1.x, h1.y, h2.x, h2.y, h3.x, h3.y};
                #pragma unroll
                for (int p = 0; p < NB; p++) {
                    ai[p] = fma2(hv[p], wib, ai[p]);
                    af[p] = fma2(hv[p], wfb, af[p]);
                    ag[p] = fma2(hv[p], wgb, ag[p]);
                    ao[p] = fma2(hv[p], wob, ao[p]);
                }
            }
        }

        __syncthreads();  // everyone done reading h_s / x_s

        // ---- gate nonlinearities + state update + h write
        #pragma unroll
        for (int p = 0; p < NB; p++) {
            float i0, i1, f0, f1, g0, g1, o0, o1;
            unpack2(ai[p], i0, i1);
            unpack2(af[p], f0, f1);
            unpack2(ag[p], g0, g1);
            unpack2(ao[p], o0, o1);
            int b0 = 2 * p, b1 = 2 * p + 1;
            {
                float iv = sigm(i0), fv = sigm(f0), gv = tanh_acc(g0), ov = sigm(o0);
                c[b0] = fv * c[b0] + iv * gv;
                h_s[j * B_BLK + b0] = ov * tanh_acc(c[b0]);
            }
            {
                float iv = sigm(i1), fv = sigm(f1), gv = tanh_acc(g1), ov = sigm(o1);
                c[b1] = fv * c[b1] + iv * gv;
                h_s[j * B_BLK + b1] = ov * tanh_acc(c[b1]);
            }
        }
    }

    __syncthreads();

    // ---- output head: out[b] = relu(sum_k h_T[b,k] * w_out[k] + b_out)
    {
        int b = j >> 4;   // 0..15
        int l = j & 15;   // 0..15
        float s = 0.0f;
        for (int k = l; k < H_DIM; k += 16)
            s += h_s[k * B_BLK + b] * __ldg(&w_out[k]);
        #pragma unroll
        for (int off = 8; off > 0; off >>= 1)
            s += __shfl_down_sync(0xffffffffu, s, off);
        if (l == 0) {
            float r = s + __ldg(&b_out[0]);
            out[B0 + b] = r > 0.0f ? r : 0.0f;
        }
    }
}

extern "C" void kernel_launch(void* const* d_in, const int* in_sizes, int n_in,
                              void* d_out, int out_size) {
    // Identify inputs by element count (all distinct) — robust to ordering.
    const float *xd = nullptr, *w_ih = nullptr, *w_hh = nullptr;
    const float *bias = nullptr, *w_out = nullptr, *b_out = nullptr;
    for (int i = 0; i < n_in; i++) {
        switch (in_sizes[i]) {
            case 4096 * 365 * 32: xd    = (const float*)d_in[i]; break;  // 47841280
            case 1024 * 32:       w_ih  = (const float*)d_in[i]; break;  // 32768
            case 1024 * 256:      w_hh  = (const float*)d_in[i]; break;  // 262144
            case 1024:            bias  = (const float*)d_in[i]; break;
            case 256:             w_out = (const float*)d_in[i]; break;
            case 1:               b_out = (const float*)d_in[i]; break;
            default: break;
        }
    }
    float* out = (float*)d_out;
    lstm_scan_kernel<<<4096 / B_BLK, 256>>>(xd, w_ih, w_hh, bias, w_out, b_out, out);
}